// round 16
// baseline (speedup 1.0000x reference)
#include <cuda_runtime.h>
#include <cuda_fp16.h>
#include <cstdint>

#define DCH 64
#define MAXN 131072
#define MAXE (1 << 21)

// Scratch (allocation-free rule: __device__ globals)
__device__ __align__(16) __half g_bufA[(size_t)MAXN * DCH]; // messages
__device__ __align__(16) __half g_bufB[(size_t)MAXN * DCH]; // finalized h
__device__ float g_dis[MAXN];
__device__ int   g_degE[MAXN];
__device__ int   g_rowptr[MAXN + 1];
__device__ int   g_cursor[MAXN];
__device__ int   g_col[MAXE];
__device__ int   g_bsum[256];

// ---------------------------------------------------------------------------
// Degree / normalization + CSR build
// ---------------------------------------------------------------------------
__global__ void count_deg_kernel(const int* __restrict__ dst, int E) {
    int e = (blockIdx.x * blockDim.x + threadIdx.x) * 4;
    if (e + 3 < E) {
        int4 d = *(const int4*)(dst + e);
        atomicAdd(&g_degE[d.x], 1);
        atomicAdd(&g_degE[d.y], 1);
        atomicAdd(&g_degE[d.z], 1);
        atomicAdd(&g_degE[d.w], 1);
    } else {
        for (int i = 0; i < 4; i++)
            if (e + i < E) atomicAdd(&g_degE[dst[e + i]], 1);
    }
}
// per-1024-chunk sums for the scan; also computes dis = rsqrt(deg+1)
__global__ void scanA_kernel(int n) {
    __shared__ int sh[256];
    int base = blockIdx.x * 1024 + threadIdx.x * 4;
    int s = 0;
#pragma unroll
    for (int i = 0; i < 4; i++) {
        int idx = base + i;
        if (idx < n) {
            int d = g_degE[idx];
            s += d;
            g_dis[idx] = rsqrtf((float)(d + 1));
        }
    }
    sh[threadIdx.x] = s;
    __syncthreads();
    for (int off = 128; off; off >>= 1) {
        if (threadIdx.x < off) sh[threadIdx.x] += sh[threadIdx.x + off];
        __syncthreads();
    }
    if (threadIdx.x == 0) g_bsum[blockIdx.x] = sh[0];
}
// warp-parallel exclusive scan of the <=256 block sums
__global__ void scanB_kernel(int nb, int n, int E) {
    int lid = threadIdx.x;  // 32 threads
    int carry = 0;
    for (int base = 0; base < nb; base += 32) {
        int i = base + lid;
        int v = (i < nb) ? g_bsum[i] : 0;
        int x = v;
#pragma unroll
        for (int off = 1; off < 32; off <<= 1) {
            int t = __shfl_up_sync(0xFFFFFFFF, x, off);
            if (lid >= off) x += t;
        }
        if (i < nb) g_bsum[i] = carry + x - v;  // exclusive
        carry += __shfl_sync(0xFFFFFFFF, x, 31);
    }
    if (lid == 0) g_rowptr[n] = E;
}
__global__ void scanC_kernel(int n) {
    __shared__ int sh[256];
    int base = blockIdx.x * 1024 + threadIdx.x * 4;
    int v[4]; int mysum = 0;
#pragma unroll
    for (int i = 0; i < 4; i++) {
        v[i] = (base + i < n) ? g_degE[base + i] : 0;
        mysum += v[i];
    }
    sh[threadIdx.x] = mysum;
    __syncthreads();
    for (int off = 1; off < 256; off <<= 1) {
        int t = (threadIdx.x >= off) ? sh[threadIdx.x - off] : 0;
        __syncthreads();
        sh[threadIdx.x] += t;
        __syncthreads();
    }
    int run = sh[threadIdx.x] - mysum + g_bsum[blockIdx.x];
#pragma unroll
    for (int i = 0; i < 4; i++) {
        if (base + i < n) {
            g_rowptr[base + i] = run;
            g_cursor[base + i] = run;
            run += v[i];
        }
    }
}
__global__ void fill_kernel(const int* __restrict__ src, const int* __restrict__ dst, int E) {
    int e = (blockIdx.x * blockDim.x + threadIdx.x) * 4;
    if (e + 3 < E) {
        int4 d = *(const int4*)(dst + e);
        int4 s = *(const int4*)(src + e);
        g_col[atomicAdd(&g_cursor[d.x], 1)] = s.x;
        g_col[atomicAdd(&g_cursor[d.y], 1)] = s.y;
        g_col[atomicAdd(&g_cursor[d.z], 1)] = s.z;
        g_col[atomicAdd(&g_cursor[d.w], 1)] = s.w;
    } else {
        for (int i = 0; i < 4; i++)
            if (e + i < E) g_col[atomicAdd(&g_cursor[dst[e + i]], 1)] = src[e + i];
    }
}

// ---------------------------------------------------------------------------
// fp16 helpers
// ---------------------------------------------------------------------------
__device__ __forceinline__ void acc_h8(float* a, uint4 v) {
    __half2 h0 = *(__half2*)&v.x, h1 = *(__half2*)&v.y;
    __half2 h2 = *(__half2*)&v.z, h3 = *(__half2*)&v.w;
    float2 f0 = __half22float2(h0), f1 = __half22float2(h1);
    float2 f2 = __half22float2(h2), f3 = __half22float2(h3);
    a[0] += f0.x; a[1] += f0.y; a[2] += f1.x; a[3] += f1.y;
    a[4] += f2.x; a[5] += f2.y; a[6] += f3.x; a[7] += f3.y;
}

// Per-thread serial CSR gather: 8 threads per node, lane owns channels
// [c*8, c*8+8). Col reads are same-address within the group (coalescer
// merges); row reads of a group are one contiguous 128B line.
// unroll 8 for deeper MLP.
__device__ __forceinline__ void gather_node(float* a, const __half* __restrict__ buf,
                                            int r, int c) {
    const uint4* gb = (const uint4*)buf;
    acc_h8(a, gb[(size_t)r * 8 + c]);            // self-loop
    int e0 = __ldg(&g_rowptr[r]), e1 = __ldg(&g_rowptr[r + 1]);
#pragma unroll 8
    for (int e = e0; e < e1; e++) {
        int s = __ldg(&g_col[e]);
        acc_h8(a, gb[(size_t)s * 8 + c]);
    }
}

// ---------------------------------------------------------------------------
// GEMM core: xs[128x64 fp32] @ Ws[64x64 fp32] -> fp16 msg (dis-scaled).
// 256 threads; thread = 4 rows x 8 cols (rt = tid>>3, ct = tid&7).
// Per k: 4 broadcast x-loads + 2 vec W-loads for 32 FMA.
// ---------------------------------------------------------------------------
__device__ __forceinline__ void gemm_core(
    const float* xs, const float* Ws, int base, int n, __half* __restrict__ dstbuf)
{
    int tid = threadIdx.x;
    int rt = tid >> 3;          // row tile 0..31 -> rows rt*4..+3
    int ct = tid & 7;           // col tile -> cols ct*8..+7

    float acc[4][8];
#pragma unroll
    for (int i = 0; i < 4; i++)
#pragma unroll
        for (int j = 0; j < 8; j++) acc[i][j] = 0.f;

#pragma unroll 8
    for (int k = 0; k < DCH; k++) {
        float4 w0 = *(const float4*)(Ws + k * DCH + ct * 8);
        float4 w1 = *(const float4*)(Ws + k * DCH + ct * 8 + 4);
#pragma unroll
        for (int i = 0; i < 4; i++) {
            float xv = xs[(rt * 4 + i) * DCH + k];
            acc[i][0] = fmaf(xv, w0.x, acc[i][0]);
            acc[i][1] = fmaf(xv, w0.y, acc[i][1]);
            acc[i][2] = fmaf(xv, w0.z, acc[i][2]);
            acc[i][3] = fmaf(xv, w0.w, acc[i][3]);
            acc[i][4] = fmaf(xv, w1.x, acc[i][4]);
            acc[i][5] = fmaf(xv, w1.y, acc[i][5]);
            acc[i][6] = fmaf(xv, w1.z, acc[i][6]);
            acc[i][7] = fmaf(xv, w1.w, acc[i][7]);
        }
    }

#pragma unroll
    for (int i = 0; i < 4; i++) {
        int r = base + rt * 4 + i;
        if (r < n) {
            float dr = g_dis[r];
            __half2 h0 = __floats2half2_rn(dr * acc[i][0], dr * acc[i][1]);
            __half2 h1 = __floats2half2_rn(dr * acc[i][2], dr * acc[i][3]);
            __half2 h2 = __floats2half2_rn(dr * acc[i][4], dr * acc[i][5]);
            __half2 h3 = __floats2half2_rn(dr * acc[i][6], dr * acc[i][7]);
            *(uint4*)(dstbuf + (size_t)r * DCH + ct * 8) =
                make_uint4(*(uint32_t*)&h0, *(uint32_t*)&h1,
                           *(uint32_t*)&h2, *(uint32_t*)&h3);
        }
    }
}

// Layer-1 GEMM: fp32 dense x -> msg in g_bufA
__global__ void __launch_bounds__(256) gemm1_kernel(
    const float* __restrict__ in, const float* __restrict__ W, int n)
{
    __shared__ float xs[128 * DCH];   // 32 KB
    __shared__ float Ws[DCH * DCH];   // 16 KB
    int tid = threadIdx.x;

#pragma unroll
    for (int i = 0; i < 4; i++)
        ((float4*)Ws)[tid + 256 * i] = ((const float4*)W)[tid + 256 * i];

    int base = blockIdx.x * 128;
    int cg = (tid & 15) * 4;
#pragma unroll
    for (int rep = 0; rep < 8; rep++) {
        int lr = (tid >> 4) + rep * 16;
        int r = base + lr;
        float4 v = make_float4(0.f, 0.f, 0.f, 0.f);
        if (r < n) v = *(const float4*)(in + (size_t)r * DCH + cg);
        *(float4*)(xs + lr * DCH + cg) = v;
    }
    __syncthreads();

    gemm_core(xs, Ws, base, n, g_bufA);
}

// Middle GEMM: fp16 finalized h -> msg in dstbuf
__global__ void __launch_bounds__(256) gemm_mid_kernel(
    const __half* __restrict__ h, __half* __restrict__ dstbuf,
    const float* __restrict__ W, int n)
{
    __shared__ float xs[128 * DCH];   // 32 KB
    __shared__ float Ws[DCH * DCH];   // 16 KB
    int tid = threadIdx.x;

#pragma unroll
    for (int i = 0; i < 4; i++)
        ((float4*)Ws)[tid + 256 * i] = ((const float4*)W)[tid + 256 * i];

    int base = blockIdx.x * 128;
    int cg = (tid & 15) * 4;
#pragma unroll
    for (int rep = 0; rep < 8; rep++) {
        int lr = (tid >> 4) + rep * 16;
        int r = base + lr;
        float4 v = make_float4(0.f, 0.f, 0.f, 0.f);
        if (r < n) {
            uint2 u = *(const uint2*)(h + (size_t)r * DCH + cg);
            float2 f0 = __half22float2(*(__half2*)&u.x);
            float2 f1 = __half22float2(*(__half2*)&u.y);
            v = make_float4(f0.x, f0.y, f1.x, f1.y);
        }
        *(float4*)(xs + lr * DCH + cg) = v;
    }
    __syncthreads();

    gemm_core(xs, Ws, base, n, dstbuf);
}

// ---------------------------------------------------------------------------
// Middle gather: h[r] = f16( relu(dis[r]*sum(msg) + b) )   (barrier-free)
// ---------------------------------------------------------------------------
__global__ void __launch_bounds__(256) gather_mid_kernel(
    const __half* __restrict__ srcbuf, __half* __restrict__ dsth,
    const float* __restrict__ b, int n)
{
    int t = blockIdx.x * blockDim.x + threadIdx.x;
    int r = t >> 3;
    if (r >= n) return;
    int c = t & 7;

    float a[8] = {0, 0, 0, 0, 0, 0, 0, 0};
    gather_node(a, srcbuf, r, c);

    float dr = g_dis[r];
    float4 b0 = *(const float4*)(b + c * 8);
    float4 b1 = *(const float4*)(b + c * 8 + 4);
    float h0 = fmaxf(fmaf(dr, a[0], b0.x), 0.f);
    float h1 = fmaxf(fmaf(dr, a[1], b0.y), 0.f);
    float h2 = fmaxf(fmaf(dr, a[2], b0.z), 0.f);
    float h3 = fmaxf(fmaf(dr, a[3], b0.w), 0.f);
    float h4 = fmaxf(fmaf(dr, a[4], b1.x), 0.f);
    float h5 = fmaxf(fmaf(dr, a[5], b1.y), 0.f);
    float h6 = fmaxf(fmaf(dr, a[6], b1.z), 0.f);
    float h7 = fmaxf(fmaf(dr, a[7], b1.w), 0.f);
    __half2 p0 = __floats2half2_rn(h0, h1);
    __half2 p1 = __floats2half2_rn(h2, h3);
    __half2 p2 = __floats2half2_rn(h4, h5);
    __half2 p3 = __floats2half2_rn(h6, h7);
    uint4 o = make_uint4(*(uint32_t*)&p0, *(uint32_t*)&p1,
                         *(uint32_t*)&p2, *(uint32_t*)&p3);
    *(uint4*)(dsth + (size_t)r * DCH + c * 8) = o;
}

// ---------------------------------------------------------------------------
// Final gather: out[r] = dis[r]*sum(srcbuf) + b3   (fp32 output)
// ---------------------------------------------------------------------------
__global__ void __launch_bounds__(256) final_gather_kernel(
    const __half* __restrict__ srcbuf,
    const float* __restrict__ b, float* __restrict__ out, int n)
{
    int t = blockIdx.x * blockDim.x + threadIdx.x;
    int r = t >> 3;
    if (r >= n) return;
    int c = t & 7;

    float a[8] = {0, 0, 0, 0, 0, 0, 0, 0};
    gather_node(a, srcbuf, r, c);

    float dr = g_dis[r];
    float4 b0 = *(const float4*)(b + c * 8);
    float4 b1 = *(const float4*)(b + c * 8 + 4);
    float4 o0, o1;
    o0.x = fmaf(dr, a[0], b0.x); o0.y = fmaf(dr, a[1], b0.y);
    o0.z = fmaf(dr, a[2], b0.z); o0.w = fmaf(dr, a[3], b0.w);
    o1.x = fmaf(dr, a[4], b1.x); o1.y = fmaf(dr, a[5], b1.y);
    o1.z = fmaf(dr, a[6], b1.z); o1.w = fmaf(dr, a[7], b1.w);
    *(float4*)(out + (size_t)r * DCH + c * 8)     = o0;
    *(float4*)(out + (size_t)r * DCH + c * 8 + 4) = o1;
}

// ---------------------------------------------------------------------------
extern "C" void kernel_launch(void* const* d_in, const int* in_sizes, int n_in,
                              void* d_out, int out_size)
{
    const float* x  = (const float*)d_in[0];
    const int*   ei = (const int*)d_in[1];
    const float* W1 = (const float*)d_in[2];
    const float* b1 = (const float*)d_in[3];
    const float* W2 = (const float*)d_in[4];
    const float* b2 = (const float*)d_in[5];
    const float* W3 = (const float*)d_in[6];
    const float* b3 = (const float*)d_in[7];
    float* out = (float*)d_out;

    int n = in_sizes[0] / DCH;
    int E = in_sizes[1] / 2;
    const int* src = ei;
    const int* dst = ei + E;

    int nb_e4  = (E + 1023) / 1024;   // 4 edges/thread
    int nb_sc  = (n + 1023) / 1024;
    int nb_gm  = (n + 127) / 128;
    int nb_gat = (int)(((long long)n * 8 + 255) / 256);

    // device pointers to the two buffers
    void* pA = nullptr; cudaGetSymbolAddress(&pA, g_bufA);
    void* pB = nullptr; cudaGetSymbolAddress(&pB, g_bufB);
    __half* bufA = (__half*)pA;
    __half* bufB = (__half*)pB;

    // normalization + CSR build (recomputed every call)
    void* degE_ptr = nullptr;
    cudaGetSymbolAddress(&degE_ptr, g_degE);
    cudaMemsetAsync(degE_ptr, 0, (size_t)n * sizeof(int));
    count_deg_kernel<<<nb_e4, 256>>>(dst, E);
    scanA_kernel<<<nb_sc, 256>>>(n);           // also computes g_dis
    scanB_kernel<<<1, 32>>>(nb_sc, n, E);
    scanC_kernel<<<nb_sc, 256>>>(n);
    fill_kernel<<<nb_e4, 256>>>(src, dst, E);

    // layer 1: dense GEMM -> msg in bufA
    gemm1_kernel<<<nb_gm, 256>>>(x, W1, n);
    // gather1 + finalize(b1): h1 fp16 -> bufB
    gather_mid_kernel<<<nb_gat, 256>>>(bufA, bufB, b1, n);
    // layer 2 GEMM: h1 @ W2 -> msg in bufA
    gemm_mid_kernel<<<nb_gm, 256>>>(bufB, bufA, W2, n);
    // gather2 + finalize(b2): h2 fp16 -> bufB
    gather_mid_kernel<<<nb_gat, 256>>>(bufA, bufB, b2, n);
    // layer 3 GEMM: h2 @ W3 -> msg in bufA
    gemm_mid_kernel<<<nb_gm, 256>>>(bufB, bufA, W3, n);
    // output: gather msg + bias b3 (fp32)
    final_gather_kernel<<<nb_gat, 256>>>(bufA, b3, out, n);
}

// round 17
// speedup vs baseline: 1.1768x; 1.1768x over previous
#include <cuda_runtime.h>
#include <cuda_fp16.h>
#include <cstdint>

#define DCH 64
#define MAXN 131072
#define MAXE (1 << 21)

// Scratch (allocation-free rule: __device__ globals)
__device__ __align__(16) __half g_bufA[(size_t)MAXN * DCH]; // messages
__device__ __align__(16) __half g_bufB[(size_t)MAXN * DCH]; // finalized h
__device__ float g_dis[MAXN];
__device__ int   g_degE[MAXN];
__device__ int   g_rowptr[MAXN + 1];
__device__ int   g_cursor[MAXN];
__device__ int   g_col[MAXE];
__device__ int   g_bsum[256];

// ---------------------------------------------------------------------------
// Degree / normalization + CSR build
// ---------------------------------------------------------------------------
__global__ void count_deg_kernel(const int* __restrict__ dst, int E) {
    int i = blockIdx.x * blockDim.x + threadIdx.x;
    if (i < E) atomicAdd(&g_degE[dst[i]], 1);
}
// per-1024-chunk sums for the scan; also computes dis = rsqrt(deg+1)
__global__ void scanA_kernel(int n) {
    __shared__ int sh[256];
    int base = blockIdx.x * 1024 + threadIdx.x * 4;
    int s = 0;
#pragma unroll
    for (int i = 0; i < 4; i++) {
        int idx = base + i;
        if (idx < n) {
            int d = g_degE[idx];
            s += d;
            g_dis[idx] = rsqrtf((float)(d + 1));
        }
    }
    sh[threadIdx.x] = s;
    __syncthreads();
    for (int off = 128; off; off >>= 1) {
        if (threadIdx.x < off) sh[threadIdx.x] += sh[threadIdx.x + off];
        __syncthreads();
    }
    if (threadIdx.x == 0) g_bsum[blockIdx.x] = sh[0];
}
// warp-parallel exclusive scan of the <=256 block sums
__global__ void scanB_kernel(int nb, int n, int E) {
    int lid = threadIdx.x;  // 32 threads
    int carry = 0;
    for (int base = 0; base < nb; base += 32) {
        int i = base + lid;
        int v = (i < nb) ? g_bsum[i] : 0;
        int x = v;
#pragma unroll
        for (int off = 1; off < 32; off <<= 1) {
            int t = __shfl_up_sync(0xFFFFFFFF, x, off);
            if (lid >= off) x += t;
        }
        if (i < nb) g_bsum[i] = carry + x - v;  // exclusive
        carry += __shfl_sync(0xFFFFFFFF, x, 31);
    }
    if (lid == 0) g_rowptr[n] = E;
}
__global__ void scanC_kernel(int n) {
    __shared__ int sh[256];
    int base = blockIdx.x * 1024 + threadIdx.x * 4;
    int v[4]; int mysum = 0;
#pragma unroll
    for (int i = 0; i < 4; i++) {
        v[i] = (base + i < n) ? g_degE[base + i] : 0;
        mysum += v[i];
    }
    sh[threadIdx.x] = mysum;
    __syncthreads();
    for (int off = 1; off < 256; off <<= 1) {
        int t = (threadIdx.x >= off) ? sh[threadIdx.x - off] : 0;
        __syncthreads();
        sh[threadIdx.x] += t;
        __syncthreads();
    }
    int run = sh[threadIdx.x] - mysum + g_bsum[blockIdx.x];
#pragma unroll
    for (int i = 0; i < 4; i++) {
        if (base + i < n) {
            g_rowptr[base + i] = run;
            g_cursor[base + i] = run;
            run += v[i];
        }
    }
}
__global__ void fill_kernel(const int* __restrict__ src, const int* __restrict__ dst, int E) {
    int e = blockIdx.x * blockDim.x + threadIdx.x;
    if (e < E) {
        int pos = atomicAdd(&g_cursor[dst[e]], 1);
        g_col[pos] = src[e];
    }
}

// ---------------------------------------------------------------------------
// fp16 helpers
// ---------------------------------------------------------------------------
__device__ __forceinline__ void acc_h8(float* a, uint4 v) {
    __half2 h0 = *(__half2*)&v.x, h1 = *(__half2*)&v.y;
    __half2 h2 = *(__half2*)&v.z, h3 = *(__half2*)&v.w;
    float2 f0 = __half22float2(h0), f1 = __half22float2(h1);
    float2 f2 = __half22float2(h2), f3 = __half22float2(h3);
    a[0] += f0.x; a[1] += f0.y; a[2] += f1.x; a[3] += f1.y;
    a[4] += f2.x; a[5] += f2.y; a[6] += f3.x; a[7] += f3.y;
}

// 16-threads-per-node CSR gather: lane owns channels [c*8,c*8+8); the two
// halves (h=0/1) take alternating edges -> 2x rows in flight per node, half
// the serial chain. Partials combined via shfl_xor(8) (partner is in-warp:
// 32 threads = 2 node-groups). h=0 lane adds self-loop and is the writer.
__device__ __forceinline__ void gather_node16(float* a, const __half* __restrict__ buf,
                                              int r, int c, int h) {
    const uint4* gb = (const uint4*)buf;
    int e0 = __ldg(&g_rowptr[r]), e1 = __ldg(&g_rowptr[r + 1]);
#pragma unroll 4
    for (int e = e0 + h; e < e1; e += 2) {
        int s = __ldg(&g_col[e]);
        acc_h8(a, gb[(size_t)s * 8 + c]);
    }
    if (h == 0) acc_h8(a, gb[(size_t)r * 8 + c]);  // self-loop
#pragma unroll
    for (int i = 0; i < 8; i++)
        a[i] += __shfl_xor_sync(0xFFFFFFFF, a[i], 8);
}

// ---------------------------------------------------------------------------
// Layer-1 GEMM (dense fp32 input x): BM=128, 256 threads, 8 rows x 4 cols/thread.
//   bufA[r] = f16( dis[r] * (x[r] @ W) )
// ---------------------------------------------------------------------------
__global__ void __launch_bounds__(256) gemm1_kernel(
    const float* __restrict__ in, const float* __restrict__ W, int n)
{
    __shared__ float xs[128 * DCH];   // 32 KB
    __shared__ float Ws[DCH * DCH];   // 16 KB
    int tid = threadIdx.x;

#pragma unroll
    for (int i = 0; i < 4; i++)
        ((float4*)Ws)[tid + 256 * i] = ((const float4*)W)[tid + 256 * i];

    int base = blockIdx.x * 128;
    int cg = (tid & 15) * 4;
#pragma unroll
    for (int rep = 0; rep < 8; rep++) {
        int lr = (tid >> 4) + rep * 16;
        int r = base + lr;
        float4 v = make_float4(0.f, 0.f, 0.f, 0.f);
        if (r < n) v = *(const float4*)(in + (size_t)r * DCH + cg);
        *(float4*)(xs + lr * DCH + cg) = v;
    }
    __syncthreads();

    int rbase = (tid >> 4) * 8;
    float4 acc[8];
#pragma unroll
    for (int i = 0; i < 8; i++) acc[i] = make_float4(0.f, 0.f, 0.f, 0.f);

#pragma unroll 8
    for (int k = 0; k < DCH; k++) {
        float4 w = *(const float4*)(Ws + k * DCH + cg);
#pragma unroll
        for (int i = 0; i < 8; i++) {
            float xv = xs[(rbase + i) * DCH + k];
            acc[i].x = fmaf(xv, w.x, acc[i].x);
            acc[i].y = fmaf(xv, w.y, acc[i].y);
            acc[i].z = fmaf(xv, w.z, acc[i].z);
            acc[i].w = fmaf(xv, w.w, acc[i].w);
        }
    }

#pragma unroll
    for (int i = 0; i < 8; i++) {
        int r = base + rbase + i;
        if (r < n) {
            float dr = g_dis[r];
            __half2 h0 = __floats2half2_rn(dr * acc[i].x, dr * acc[i].y);
            __half2 h1 = __floats2half2_rn(dr * acc[i].z, dr * acc[i].w);
            *(uint2*)(g_bufA + (size_t)r * DCH + cg) =
                make_uint2(*(uint32_t*)&h0, *(uint32_t*)&h1);
        }
    }
}

// ---------------------------------------------------------------------------
// Middle GEMM (fp16 finalized input h): same tiling, converts h->fp32 in smem.
//   dstbuf[r] = f16( dis[r] * (h[r] @ W) )
// ---------------------------------------------------------------------------
__global__ void __launch_bounds__(256) gemm_mid_kernel(
    const __half* __restrict__ h, __half* __restrict__ dstbuf,
    const float* __restrict__ W, int n)
{
    __shared__ float xs[128 * DCH];   // 32 KB
    __shared__ float Ws[DCH * DCH];   // 16 KB
    int tid = threadIdx.x;

#pragma unroll
    for (int i = 0; i < 4; i++)
        ((float4*)Ws)[tid + 256 * i] = ((const float4*)W)[tid + 256 * i];

    int base = blockIdx.x * 128;
    int cg = (tid & 15) * 4;
#pragma unroll
    for (int rep = 0; rep < 8; rep++) {
        int lr = (tid >> 4) + rep * 16;
        int r = base + lr;
        float4 v = make_float4(0.f, 0.f, 0.f, 0.f);
        if (r < n) {
            uint2 u = *(const uint2*)(h + (size_t)r * DCH + cg);
            float2 f0 = __half22float2(*(__half2*)&u.x);
            float2 f1 = __half22float2(*(__half2*)&u.y);
            v = make_float4(f0.x, f0.y, f1.x, f1.y);
        }
        *(float4*)(xs + lr * DCH + cg) = v;
    }
    __syncthreads();

    int rbase = (tid >> 4) * 8;
    float4 acc[8];
#pragma unroll
    for (int i = 0; i < 8; i++) acc[i] = make_float4(0.f, 0.f, 0.f, 0.f);

#pragma unroll 8
    for (int k = 0; k < DCH; k++) {
        float4 w = *(const float4*)(Ws + k * DCH + cg);
#pragma unroll
        for (int i = 0; i < 8; i++) {
            float xv = xs[(rbase + i) * DCH + k];
            acc[i].x = fmaf(xv, w.x, acc[i].x);
            acc[i].y = fmaf(xv, w.y, acc[i].y);
            acc[i].z = fmaf(xv, w.z, acc[i].z);
            acc[i].w = fmaf(xv, w.w, acc[i].w);
        }
    }

#pragma unroll
    for (int i = 0; i < 8; i++) {
        int r = base + rbase + i;
        if (r < n) {
            float dr = g_dis[r];
            __half2 h0 = __floats2half2_rn(dr * acc[i].x, dr * acc[i].y);
            __half2 h1 = __floats2half2_rn(dr * acc[i].z, dr * acc[i].w);
            *(uint2*)(dstbuf + (size_t)r * DCH + cg) =
                make_uint2(*(uint32_t*)&h0, *(uint32_t*)&h1);
        }
    }
}

// ---------------------------------------------------------------------------
// Middle gather: h[r] = f16( relu(dis[r]*sum(msg) + b) )   (16 thr/node)
// ---------------------------------------------------------------------------
__global__ void __launch_bounds__(256) gather_mid_kernel(
    const __half* __restrict__ srcbuf, __half* __restrict__ dsth,
    const float* __restrict__ b, int n)
{
    int t = blockIdx.x * blockDim.x + threadIdx.x;
    int r = t >> 4;
    if (r >= n) return;
    int c = t & 7;
    int h = (t >> 3) & 1;

    float a[8] = {0, 0, 0, 0, 0, 0, 0, 0};
    gather_node16(a, srcbuf, r, c, h);
    if (h) return;   // h=0 lane writes

    float dr = g_dis[r];
    float4 b0 = *(const float4*)(b + c * 8);
    float4 b1 = *(const float4*)(b + c * 8 + 4);
    float h0 = fmaxf(fmaf(dr, a[0], b0.x), 0.f);
    float h1 = fmaxf(fmaf(dr, a[1], b0.y), 0.f);
    float h2 = fmaxf(fmaf(dr, a[2], b0.z), 0.f);
    float h3 = fmaxf(fmaf(dr, a[3], b0.w), 0.f);
    float h4 = fmaxf(fmaf(dr, a[4], b1.x), 0.f);
    float h5 = fmaxf(fmaf(dr, a[5], b1.y), 0.f);
    float h6 = fmaxf(fmaf(dr, a[6], b1.z), 0.f);
    float h7 = fmaxf(fmaf(dr, a[7], b1.w), 0.f);
    __half2 p0 = __floats2half2_rn(h0, h1);
    __half2 p1 = __floats2half2_rn(h2, h3);
    __half2 p2 = __floats2half2_rn(h4, h5);
    __half2 p3 = __floats2half2_rn(h6, h7);
    uint4 o = make_uint4(*(uint32_t*)&p0, *(uint32_t*)&p1,
                         *(uint32_t*)&p2, *(uint32_t*)&p3);
    *(uint4*)(dsth + (size_t)r * DCH + c * 8) = o;
}

// ---------------------------------------------------------------------------
// Final gather: out[r] = dis[r]*sum(srcbuf) + b3   (fp32 output, 16 thr/node)
// ---------------------------------------------------------------------------
__global__ void __launch_bounds__(256) final_gather_kernel(
    const __half* __restrict__ srcbuf,
    const float* __restrict__ b, float* __restrict__ out, int n)
{
    int t = blockIdx.x * blockDim.x + threadIdx.x;
    int r = t >> 4;
    if (r >= n) return;
    int c = t & 7;
    int h = (t >> 3) & 1;

    float a[8] = {0, 0, 0, 0, 0, 0, 0, 0};
    gather_node16(a, srcbuf, r, c, h);
    if (h) return;

    float dr = g_dis[r];
    float4 b0 = *(const float4*)(b + c * 8);
    float4 b1 = *(const float4*)(b + c * 8 + 4);
    float4 o0, o1;
    o0.x = fmaf(dr, a[0], b0.x); o0.y = fmaf(dr, a[1], b0.y);
    o0.z = fmaf(dr, a[2], b0.z); o0.w = fmaf(dr, a[3], b0.w);
    o1.x = fmaf(dr, a[4], b1.x); o1.y = fmaf(dr, a[5], b1.y);
    o1.z = fmaf(dr, a[6], b1.z); o1.w = fmaf(dr, a[7], b1.w);
    *(float4*)(out + (size_t)r * DCH + c * 8)     = o0;
    *(float4*)(out + (size_t)r * DCH + c * 8 + 4) = o1;
}

// ---------------------------------------------------------------------------
extern "C" void kernel_launch(void* const* d_in, const int* in_sizes, int n_in,
                              void* d_out, int out_size)
{
    const float* x  = (const float*)d_in[0];
    const int*   ei = (const int*)d_in[1];
    const float* W1 = (const float*)d_in[2];
    const float* b1 = (const float*)d_in[3];
    const float* W2 = (const float*)d_in[4];
    const float* b2 = (const float*)d_in[5];
    const float* W3 = (const float*)d_in[6];
    const float* b3 = (const float*)d_in[7];
    float* out = (float*)d_out;

    int n = in_sizes[0] / DCH;
    int E = in_sizes[1] / 2;
    const int* src = ei;
    const int* dst = ei + E;

    int nb_e   = (E + 255) / 256;
    int nb_sc  = (n + 1023) / 1024;
    int nb_gm  = (n + 127) / 128;
    int nb_gat = (int)(((long long)n * 16 + 255) / 256);

    // device pointers to the two buffers
    void* pA = nullptr; cudaGetSymbolAddress(&pA, g_bufA);
    void* pB = nullptr; cudaGetSymbolAddress(&pB, g_bufB);
    __half* bufA = (__half*)pA;
    __half* bufB = (__half*)pB;

    // normalization + CSR build (recomputed every call)
    void* degE_ptr = nullptr;
    cudaGetSymbolAddress(&degE_ptr, g_degE);
    cudaMemsetAsync(degE_ptr, 0, (size_t)n * sizeof(int));
    count_deg_kernel<<<nb_e, 256>>>(dst, E);
    scanA_kernel<<<nb_sc, 256>>>(n);           // also computes g_dis
    scanB_kernel<<<1, 32>>>(nb_sc, n, E);
    scanC_kernel<<<nb_sc, 256>>>(n);
    fill_kernel<<<nb_e, 256>>>(src, dst, E);

    // layer 1: dense GEMM -> msg in bufA
    gemm1_kernel<<<nb_gm, 256>>>(x, W1, n);
    // gather1 + finalize(b1): h1 fp16 -> bufB
    gather_mid_kernel<<<nb_gat, 256>>>(bufA, bufB, b1, n);
    // layer 2 GEMM: h1 @ W2 -> msg in bufA
    gemm_mid_kernel<<<nb_gm, 256>>>(bufB, bufA, W2, n);
    // gather2 + finalize(b2): h2 fp16 -> bufB
    gather_mid_kernel<<<nb_gat, 256>>>(bufA, bufB, b2, n);
    // layer 3 GEMM: h2 @ W3 -> msg in bufA
    gemm_mid_kernel<<<nb_gm, 256>>>(bufB, bufA, W3, n);
    // output: gather msg + bias b3 (fp32)
    final_gather_kernel<<<nb_gat, 256>>>(bufA, b3, out, n);
}